// round 16
// baseline (speedup 1.0000x reference)
#include <cuda_runtime.h>
#include <cuda_bf16.h>
#include <cuda_fp16.h>
#include <cstdint>
#include <cstddef>

#define BATCH   4
#define SLEN    4096
#define DDIM    1024
#define MTOT    (BATCH * SLEN)          // 16384

typedef __nv_bfloat16  bf16;
typedef __nv_bfloat162 bf162;

// ---------------------------------------------------------------------------
// Scratch (allocation-free rule: __device__ globals).
// z path (bf16 3-pass):   z = x·M, M = Wqᵀ·Wk           (K projection gone)
// scores (fp16 2-pass):   scores = (zh+zl)·x16ᵀ  (fp32 out)
// PV path (fp16 1-pass):  Vᵀ = Wvh·x16ᵀ, attended = P16·Vᵀᵀ  (128x64 tiles)
// ---------------------------------------------------------------------------
__device__ bf16 g_xhi [(size_t)MTOT * DDIM];
__device__ bf16 g_xlo [(size_t)MTOT * DDIM];
__device__ bf16 g_Wqthi[(size_t)DDIM * DDIM];
__device__ bf16 g_Wqtlo[(size_t)DDIM * DDIM];
__device__ bf16 g_Wkthi[(size_t)DDIM * DDIM];
__device__ bf16 g_Wktlo[(size_t)DDIM * DDIM];
__device__ bf16 g_Mthi[(size_t)DDIM * DDIM];
__device__ bf16 g_Mtlo[(size_t)DDIM * DDIM];
__device__ float g_S  [(size_t)MTOT * SLEN];
// fp16 operands
__device__ __half g_x16 [(size_t)MTOT * DDIM];   // x rounded to fp16
__device__ __half g_zh16[(size_t)MTOT * DDIM];   // z split fp16
__device__ __half g_zl16[(size_t)MTOT * DDIM];
__device__ __half g_Wvh [(size_t)DDIM * DDIM];   // Wv rounded fp16
__device__ __half g_Vt16[(size_t)DDIM * MTOT];   // Vᵀ fp16 [D, MTOT]
__device__ __half g_Ph  [(size_t)MTOT * SLEN];   // P rounded fp16

// ---------------------------------------------------------------------------
// Helpers (arch-agnostic PTX only: plain sm_103 target)
// ---------------------------------------------------------------------------
__device__ __forceinline__ uint32_t smem_u32(const void* p) {
    uint32_t a;
    asm("{ .reg .u64 t; cvta.to.shared.u64 t, %1; cvt.u32.u64 %0, t; }" : "=r"(a) : "l"(p));
    return a;
}
__device__ __forceinline__ void ldsm4(uint32_t& r0, uint32_t& r1, uint32_t& r2, uint32_t& r3,
                                      uint32_t addr) {
    asm volatile("ldmatrix.sync.aligned.m8n8.x4.shared.b16 {%0,%1,%2,%3}, [%4];"
                 : "=r"(r0), "=r"(r1), "=r"(r2), "=r"(r3) : "r"(addr));
}
__device__ __forceinline__ void mma16816(float* c, const uint32_t* a, const uint32_t* b) {
    asm volatile(
        "mma.sync.aligned.m16n8k16.row.col.f32.bf16.bf16.f32 "
        "{%0,%1,%2,%3}, {%4,%5,%6,%7}, {%8,%9}, {%0,%1,%2,%3};"
        : "+f"(c[0]), "+f"(c[1]), "+f"(c[2]), "+f"(c[3])
        : "r"(a[0]), "r"(a[1]), "r"(a[2]), "r"(a[3]), "r"(b[0]), "r"(b[1]));
}
__device__ __forceinline__ void mma16816h(float* c, const uint32_t* a, const uint32_t* b) {
    asm volatile(
        "mma.sync.aligned.m16n8k16.row.col.f32.f16.f16.f32 "
        "{%0,%1,%2,%3}, {%4,%5,%6,%7}, {%8,%9}, {%0,%1,%2,%3};"
        : "+f"(c[0]), "+f"(c[1]), "+f"(c[2]), "+f"(c[3])
        : "r"(a[0]), "r"(a[1]), "r"(a[2]), "r"(a[3]), "r"(b[0]), "r"(b[1]));
}
__device__ __forceinline__ void cpasync16(uint32_t dst, const void* src) {
    asm volatile("cp.async.cg.shared.global [%0], [%1], 16;" :: "r"(dst), "l"(src));
}
__device__ __forceinline__ void split2(float x, float y, bf162& h, bf162& l) {
    h = __floats2bfloat162_rn(x, y);
    float2 f = __bfloat1622float2(h);
    l = __floats2bfloat162_rn(x - f.x, y - f.y);
}
__device__ __forceinline__ void split2h(float x, float y, __half2& h, __half2& l) {
    h = __floats2half2_rn(x, y);
    float2 f = __half22float2(h);
    l = __floats2half2_rn(x - f.x, y - f.y);
}

// ---------------------------------------------------------------------------
// Fused conversion for x: one read -> bf16 hi/lo + fp16 rounded.
// ---------------------------------------------------------------------------
__global__ __launch_bounds__(256) void conv_x(
    const float* __restrict__ src, bf16* __restrict__ hi, bf16* __restrict__ lo,
    __half* __restrict__ h16)
{
    size_t i = ((size_t)blockIdx.x * 256 + threadIdx.x) * 4;
    float4 v = *(const float4*)(src + i);
    bf162 h0, l0, h1, l1;
    split2(v.x, v.y, h0, l0);
    split2(v.z, v.w, h1, l1);
    *(bf162*)(hi + i)     = h0;
    *(bf162*)(hi + i + 2) = h1;
    *(bf162*)(lo + i)     = l0;
    *(bf162*)(lo + i + 2) = l1;
    *(__half2*)(h16 + i)     = __floats2half2_rn(v.x, v.y);
    *(__half2*)(h16 + i + 2) = __floats2half2_rn(v.z, v.w);
}

__global__ __launch_bounds__(256) void conv_round16(
    const float* __restrict__ src, __half* __restrict__ dst)
{
    size_t i = ((size_t)blockIdx.x * 256 + threadIdx.x) * 4;
    float4 v = *(const float4*)(src + i);
    *(__half2*)(dst + i)     = __floats2half2_rn(v.x, v.y);
    *(__half2*)(dst + i + 2) = __floats2half2_rn(v.z, v.w);
}

// Transpose + split: out[i,e] = src[e,i] for 1024x1024 fp32, bf16 hi/lo out.
__global__ __launch_bounds__(256) void trans_split(
    const float* __restrict__ src, bf16* __restrict__ hi, bf16* __restrict__ lo)
{
    __shared__ float t[32][33];
    const int tx = threadIdx.x & 31;
    const int ty = threadIdx.x >> 5;
    const int bx = blockIdx.x * 32;
    const int by = blockIdx.y * 32;
    #pragma unroll
    for (int i = 0; i < 4; i++)
        t[ty + i * 8][tx] = src[(size_t)(by + ty + i * 8) * DDIM + bx + tx];
    __syncthreads();
    #pragma unroll
    for (int i = 0; i < 4; i++) {
        const int r = ty + i * 8;
        float v = t[tx][r];
        bf16 h = __float2bfloat16_rn(v);
        bf16 l = __float2bfloat16_rn(v - __bfloat162float(h));
        hi[(size_t)(bx + r) * DDIM + by + tx] = h;
        lo[(size_t)(bx + r) * DDIM + by + tx] = l;
    }
}

// ---------------------------------------------------------------------------
// bf16 NT GEMM, 3-pass fp32 emulation. 128x128, KC=32, 2-stage cp.async,
// 2 CTAs/SM. mode 1: bf16 hi/lo out. mode 4: fp16 hi/lo out.
// ---------------------------------------------------------------------------
#define KC       32
#define LDT      40
#define MAT_B    (128 * LDT * 2)            // 10240 B
#define STAGE_B  (4 * MAT_B)                // 40960 B
#define SMEM_DYN (2 * STAGE_B)              // 81920 B

__global__ __launch_bounds__(256, 2) void gemm_bf(
    const bf16* __restrict__ Ahi, const bf16* __restrict__ Alo,
    const bf16* __restrict__ Bhi, const bf16* __restrict__ Blo,
    bf16* __restrict__ Chi, bf16* __restrict__ Clo,
    int lda, int ldb, int ldc, int K, int mode)
{
    extern __shared__ char smem[];

    const int tid  = threadIdx.x;
    const int lane = tid & 31;
    const int wid  = tid >> 5;
    const int bm   = blockIdx.y * 128;
    const int bn   = blockIdx.x * 128;
    const int m_warp = (wid & 3) * 32;
    const int n_warp = (wid >> 2) * 64;

    const uint32_t sbase = smem_u32(smem);
    const uint32_t aoff = (uint32_t)((m_warp + (lane & 15)) * (LDT * 2) + ((lane >> 4) * 8) * 2);
    const uint32_t boff = (uint32_t)((n_warp + (lane & 7) + ((lane & 16) ? 8 : 0)) * (LDT * 2)
                                     + ((lane & 8) ? 8 : 0) * 2);

    float acc[2][8][4];
    #pragma unroll
    for (int t = 0; t < 2; t++)
        #pragma unroll
        for (int n = 0; n < 8; n++)
            #pragma unroll
            for (int q = 0; q < 4; q++) acc[t][n][q] = 0.0f;

    const int nk = K / KC;

    auto issue = [&](int buf, int c) {
        const int k0 = c * KC;
        const uint32_t sb = sbase + buf * STAGE_B;
        #pragma unroll
        for (int i = 0; i < 2; i++) {
            const int l   = tid + i * 256;
            const int row = l >> 2;
            const int ch  = (l & 3) * 16;
            const uint32_t soff = (uint32_t)(row * (LDT * 2)) + ch;
            const size_t ga = (size_t)(bm + row) * lda + k0;
            const size_t gb = (size_t)(bn + row) * ldb + k0;
            cpasync16(sb + 0 * MAT_B + soff, (const char*)(Ahi + ga) + ch);
            cpasync16(sb + 1 * MAT_B + soff, (const char*)(Alo + ga) + ch);
            cpasync16(sb + 2 * MAT_B + soff, (const char*)(Bhi + gb) + ch);
            cpasync16(sb + 3 * MAT_B + soff, (const char*)(Blo + gb) + ch);
        }
    };

    auto compute = [&](int buf) {
        const uint32_t base = sbase + buf * STAGE_B;
        #pragma unroll
        for (int ks = 0; ks < 2; ks++) {
            const uint32_t kb = (uint32_t)ks * 32;
            uint32_t bh[4][4], bl[4][4];
            #pragma unroll
            for (int u = 0; u < 4; u++) {
                ldsm4(bh[u][0], bh[u][1], bh[u][2], bh[u][3],
                      base + 2 * MAT_B + boff + u * (16 * LDT * 2) + kb);
                ldsm4(bl[u][0], bl[u][1], bl[u][2], bl[u][3],
                      base + 3 * MAT_B + boff + u * (16 * LDT * 2) + kb);
            }
            #pragma unroll
            for (int t = 0; t < 2; t++) {
                uint32_t ah[4], al[4];
                ldsm4(ah[0], ah[1], ah[2], ah[3],
                      base + 0 * MAT_B + aoff + t * (16 * LDT * 2) + kb);
                ldsm4(al[0], al[1], al[2], al[3],
                      base + 1 * MAT_B + aoff + t * (16 * LDT * 2) + kb);
                #pragma unroll
                for (int n = 0; n < 8; n++)
                    mma16816(acc[t][n], ah, &bh[n >> 1][(n & 1) * 2]);
                #pragma unroll
                for (int n = 0; n < 8; n++)
                    mma16816(acc[t][n], ah, &bl[n >> 1][(n & 1) * 2]);
                #pragma unroll
                for (int n = 0; n < 8; n++)
                    mma16816(acc[t][n], al, &bh[n >> 1][(n & 1) * 2]);
            }
        }
    };

    issue(0, 0);
    asm volatile("cp.async.commit_group;" ::: "memory");

    for (int c = 0; c < nk; ++c) {
        asm volatile("cp.async.wait_group 0;" ::: "memory");
        __syncthreads();
        if (c + 1 < nk) {
            issue((c + 1) & 1, c + 1);
            asm volatile("cp.async.commit_group;" ::: "memory");
        }
        compute(c & 1);
    }

    #pragma unroll
    for (int t = 0; t < 2; t++)
        #pragma unroll
        for (int n = 0; n < 8; n++) {
            const int row = bm + m_warp + t * 16 + (lane >> 2);
            const int col = bn + n_warp + n * 8 + (lane & 3) * 2;
            if (mode == 1) {
                bf162 h, l;
                split2(acc[t][n][0], acc[t][n][1], h, l);
                *(bf162*)(Chi + (size_t)row * ldc + col) = h;
                *(bf162*)(Clo + (size_t)row * ldc + col) = l;
                split2(acc[t][n][2], acc[t][n][3], h, l);
                *(bf162*)(Chi + (size_t)(row + 8) * ldc + col) = h;
                *(bf162*)(Clo + (size_t)(row + 8) * ldc + col) = l;
            } else {   // mode 4: fp16 hi/lo via reinterpreted pointers
                __half* Hh = (__half*)Chi;
                __half* Hl = (__half*)Clo;
                __half2 h, l;
                split2h(acc[t][n][0], acc[t][n][1], h, l);
                *(__half2*)(Hh + (size_t)row * ldc + col) = h;
                *(__half2*)(Hl + (size_t)row * ldc + col) = l;
                split2h(acc[t][n][2], acc[t][n][3], h, l);
                *(__half2*)(Hh + (size_t)(row + 8) * ldc + col) = h;
                *(__half2*)(Hl + (size_t)(row + 8) * ldc + col) = l;
            }
        }
}

// ---------------------------------------------------------------------------
// fp16 NT GEMM, 2-pass (A split fp16, B rounded fp16), fp32 out (scores).
// ---------------------------------------------------------------------------
#define H2_STAGE (3 * MAT_B)                // Ah, Al, Bh = 30720 B
#define H2_SMEM  (2 * H2_STAGE)             // 61440 B

__global__ __launch_bounds__(256, 2) void gemm_h2(
    const __half* __restrict__ Ah, const __half* __restrict__ Al,
    const __half* __restrict__ Bh,
    float* __restrict__ Cf,
    int lda, int ldb, int ldc, int K,
    size_t sA, size_t sB, size_t sC)
{
    extern __shared__ char smem[];
    Ah += (size_t)blockIdx.z * sA;  Al += (size_t)blockIdx.z * sA;
    Bh += (size_t)blockIdx.z * sB;

    const int tid  = threadIdx.x;
    const int lane = tid & 31;
    const int wid  = tid >> 5;
    const int bm   = blockIdx.y * 128;
    const int bn   = blockIdx.x * 128;
    const int m_warp = (wid & 3) * 32;
    const int n_warp = (wid >> 2) * 64;

    const uint32_t sbase = smem_u32(smem);
    const uint32_t aoff = (uint32_t)((m_warp + (lane & 15)) * (LDT * 2) + ((lane >> 4) * 8) * 2);
    const uint32_t boff = (uint32_t)((n_warp + (lane & 7) + ((lane & 16) ? 8 : 0)) * (LDT * 2)
                                     + ((lane & 8) ? 8 : 0) * 2);

    float acc[2][8][4];
    #pragma unroll
    for (int t = 0; t < 2; t++)
        #pragma unroll
        for (int n = 0; n < 8; n++)
            #pragma unroll
            for (int q = 0; q < 4; q++) acc[t][n][q] = 0.0f;

    const int nk = K / KC;

    auto issue = [&](int buf, int c) {
        const int k0 = c * KC;
        const uint32_t sb = sbase + buf * H2_STAGE;
        #pragma unroll
        for (int i = 0; i < 2; i++) {
            const int l   = tid + i * 256;
            const int row = l >> 2;
            const int ch  = (l & 3) * 16;
            const uint32_t soff = (uint32_t)(row * (LDT * 2)) + ch;
            const size_t ga = (size_t)(bm + row) * lda + k0;
            const size_t gb = (size_t)(bn + row) * ldb + k0;
            cpasync16(sb + 0 * MAT_B + soff, (const char*)(Ah + ga) + ch);
            cpasync16(sb + 1 * MAT_B + soff, (const char*)(Al + ga) + ch);
            cpasync16(sb + 2 * MAT_B + soff, (const char*)(Bh + gb) + ch);
        }
    };

    auto compute = [&](int buf) {
        const uint32_t base = sbase + buf * H2_STAGE;
        #pragma unroll
        for (int ks = 0; ks < 2; ks++) {
            const uint32_t kb = (uint32_t)ks * 32;
            uint32_t bh[4][4];
            #pragma unroll
            for (int u = 0; u < 4; u++)
                ldsm4(bh[u][0], bh[u][1], bh[u][2], bh[u][3],
                      base + 2 * MAT_B + boff + u * (16 * LDT * 2) + kb);
            #pragma unroll
            for (int t = 0; t < 2; t++) {
                uint32_t ah[4], al[4];
                ldsm4(ah[0], ah[1], ah[2], ah[3],
                      base + 0 * MAT_B + aoff + t * (16 * LDT * 2) + kb);
                ldsm4(al[0], al[1], al[2], al[3],
                      base + 1 * MAT_B + aoff + t * (16 * LDT * 2) + kb);
                #pragma unroll
                for (int n = 0; n < 8; n++)
                    mma16816h(acc[t][n], ah, &bh[n >> 1][(n & 1) * 2]);
                #pragma unroll
                for (int n = 0; n < 8; n++)
                    mma16816h(acc[t][n], al, &bh[n >> 1][(n & 1) * 2]);
            }
        }
    };

    issue(0, 0);
    asm volatile("cp.async.commit_group;" ::: "memory");

    for (int c = 0; c < nk; ++c) {
        asm volatile("cp.async.wait_group 0;" ::: "memory");
        __syncthreads();
        if (c + 1 < nk) {
            issue((c + 1) & 1, c + 1);
            asm volatile("cp.async.commit_group;" ::: "memory");
        }
        compute(c & 1);
    }

    float* C0 = Cf + (size_t)blockIdx.z * sC;
    #pragma unroll
    for (int t = 0; t < 2; t++)
        #pragma unroll
        for (int n = 0; n < 8; n++) {
            const int row = bm + m_warp + t * 16 + (lane >> 2);
            const int col = bn + n_warp + n * 8 + (lane & 3) * 2;
            *(float2*)(C0 + (size_t)row * ldc + col) =
                make_float2(acc[t][n][0], acc[t][n][1]);
            *(float2*)(C0 + (size_t)(row + 8) * ldc + col) =
                make_float2(acc[t][n][2], acc[t][n][3]);
        }
}

// ---------------------------------------------------------------------------
// fp16 NT GEMM, 1-pass, tile 128x64 (warp tile 32x32) — finer grid to reduce
// wave quantization. mode 0: fp32 C. mode 3: fp16 rounded C.
// ---------------------------------------------------------------------------
#define B64_B     (64 * LDT * 2)            // 5120 B (B tile, 64 rows)
#define H1_STAGE  (MAT_B + B64_B)           // 15360 B
#define H1_SMEM   (2 * H1_STAGE)            // 30720 B

__global__ __launch_bounds__(256, 2) void gemm_h1_n64(
    const __half* __restrict__ Ah, const __half* __restrict__ Bh,
    float* __restrict__ Cf, __half* __restrict__ C16,
    int lda, int ldb, int ldc, int K, int mode,
    size_t sA, size_t sB, size_t sC)
{
    extern __shared__ char smem[];
    Ah += (size_t)blockIdx.z * sA;
    Bh += (size_t)blockIdx.z * sB;

    const int tid  = threadIdx.x;
    const int lane = tid & 31;
    const int wid  = tid >> 5;
    const int bm   = blockIdx.y * 128;
    const int bn   = blockIdx.x * 64;
    const int m_warp = (wid & 3) * 32;
    const int n_warp = (wid >> 2) * 32;

    const uint32_t sbase = smem_u32(smem);
    const uint32_t aoff = (uint32_t)((m_warp + (lane & 15)) * (LDT * 2) + ((lane >> 4) * 8) * 2);
    const uint32_t boff = (uint32_t)((n_warp + (lane & 7) + ((lane & 16) ? 8 : 0)) * (LDT * 2)
                                     + ((lane & 8) ? 8 : 0) * 2);

    float acc[2][4][4];
    #pragma unroll
    for (int t = 0; t < 2; t++)
        #pragma unroll
        for (int n = 0; n < 4; n++)
            #pragma unroll
            for (int q = 0; q < 4; q++) acc[t][n][q] = 0.0f;

    const int nk = K / KC;

    auto issue = [&](int buf, int c) {
        const int k0 = c * KC;
        const uint32_t sb = sbase + buf * H1_STAGE;
        // A: 128 rows x 4 chunks = 512 loads, 2/thread
        #pragma unroll
        for (int i = 0; i < 2; i++) {
            const int l   = tid + i * 256;
            const int row = l >> 2;
            const int ch  = (l & 3) * 16;
            const uint32_t soff = (uint32_t)(row * (LDT * 2)) + ch;
            const size_t ga = (size_t)(bm + row) * lda + k0;
            cpasync16(sb + soff, (const char*)(Ah + ga) + ch);
        }
        // B: 64 rows x 4 chunks = 256 loads, 1 per thread (tid < 256)
        {
            const int row = tid >> 2;
            const int ch  = (tid & 3) * 16;
            const uint32_t soff = (uint32_t)(row * (LDT * 2)) + ch;
            const size_t gb = (size_t)(bn + row) * ldb + k0;
            cpasync16(sb + MAT_B + soff, (const char*)(Bh + gb) + ch);
        }
    };

    auto compute = [&](int buf) {
        const uint32_t base = sbase + buf * H1_STAGE;
        #pragma unroll
        for (int ks = 0; ks < 2; ks++) {
            const uint32_t kb = (uint32_t)ks * 32;
            uint32_t bh[2][4];
            #pragma unroll
            for (int u = 0; u < 2; u++)
                ldsm4(bh[u][0], bh[u][1], bh[u][2], bh[u][3],
                      base + MAT_B + boff + u * (16 * LDT * 2) + kb);
            #pragma unroll
            for (int t = 0; t < 2; t++) {
                uint32_t ah[4];
                ldsm4(ah[0], ah[1], ah[2], ah[3],
                      base + aoff + t * (16 * LDT * 2) + kb);
                #pragma unroll
                for (int n = 0; n < 4; n++)
                    mma16816h(acc[t][n], ah, &bh[n >> 1][(n & 1) * 2]);
            }
        }
    };

    issue(0, 0);
    asm volatile("cp.async.commit_group;" ::: "memory");

    for (int c = 0; c < nk; ++c) {
        asm volatile("cp.async.wait_group 0;" ::: "memory");
        __syncthreads();
        if (c + 1 < nk) {
            issue((c + 1) & 1, c + 1);
            asm volatile("cp.async.commit_group;" ::: "memory");
        }
        compute(c & 1);
    }

    #pragma unroll
    for (int t = 0; t < 2; t++)
        #pragma unroll
        for (int n = 0; n < 4; n++) {
            const int row = bm + m_warp + t * 16 + (lane >> 2);
            const int col = bn + n_warp + n * 8 + (lane & 3) * 2;
            if (mode == 0) {
                float* C0 = Cf + (size_t)blockIdx.z * sC;
                *(float2*)(C0 + (size_t)row * ldc + col) =
                    make_float2(acc[t][n][0], acc[t][n][1]);
                *(float2*)(C0 + (size_t)(row + 8) * ldc + col) =
                    make_float2(acc[t][n][2], acc[t][n][3]);
            } else {   // mode 3: fp16 rounded
                *(__half2*)(C16 + (size_t)row * ldc + col) =
                    __floats2half2_rn(acc[t][n][0], acc[t][n][1]);
                *(__half2*)(C16 + (size_t)(row + 8) * ldc + col) =
                    __floats2half2_rn(acc[t][n][2], acc[t][n][3]);
            }
        }
}

// ---------------------------------------------------------------------------
// Row softmax over 4096 fp32 scores -> fp16 rounded probabilities.
// ---------------------------------------------------------------------------
__global__ __launch_bounds__(256) void softmax_kernel16(
    const float* __restrict__ Sm, __half* __restrict__ Ph)
{
    const float* row = Sm + (size_t)blockIdx.x * SLEN;
    __half* ph = Ph + (size_t)blockIdx.x * SLEN;
    const int t    = threadIdx.x;
    const int lane = t & 31;
    const int warp = t >> 5;

    __shared__ float red[8];

    float v[16];
    float mx = -1e30f;
    #pragma unroll
    for (int i = 0; i < 16; i++) {
        v[i] = row[t + (i << 8)];
        mx = fmaxf(mx, v[i]);
    }
    #pragma unroll
    for (int o = 16; o > 0; o >>= 1)
        mx = fmaxf(mx, __shfl_xor_sync(0xffffffffu, mx, o));
    if (lane == 0) red[warp] = mx;
    __syncthreads();
    float rmax = red[0];
    #pragma unroll
    for (int i = 1; i < 8; i++) rmax = fmaxf(rmax, red[i]);

    float sum = 0.0f;
    #pragma unroll
    for (int i = 0; i < 16; i++) {
        v[i] = __expf(v[i] - rmax);
        sum += v[i];
    }
    #pragma unroll
    for (int o = 16; o > 0; o >>= 1)
        sum += __shfl_xor_sync(0xffffffffu, sum, o);
    __syncthreads();
    if (lane == 0) red[warp] = sum;
    __syncthreads();
    float rsum = 0.0f;
    #pragma unroll
    for (int i = 0; i < 8; i++) rsum += red[i];

    const float inv = 1.0f / rsum;
    #pragma unroll
    for (int i = 0; i < 16; i++)
        ph[t + (i << 8)] = __float2half_rn(v[i] * inv);
}

// ---------------------------------------------------------------------------
// Final epilogue: y = attended + x;  out = y / ||y||_2 per 1024-row.
// ---------------------------------------------------------------------------
__global__ __launch_bounds__(256) void epilogue_kernel(
    const float* __restrict__ x, float* __restrict__ out)
{
    const size_t base = (size_t)blockIdx.x * DDIM;
    const int t    = threadIdx.x;
    const int lane = t & 31;
    const int warp = t >> 5;

    __shared__ float red[8];

    float4 a  = *(const float4*)(out + base + t * 4);
    float4 xv = *(const float4*)(x   + base + t * 4);
    float y0 = a.x + xv.x, y1 = a.y + xv.y, y2 = a.z + xv.z, y3 = a.w + xv.w;

    float ss = y0 * y0 + y1 * y1 + y2 * y2 + y3 * y3;
    #pragma unroll
    for (int o = 16; o > 0; o >>= 1)
        ss += __shfl_xor_sync(0xffffffffu, ss, o);
    if (lane == 0) red[warp] = ss;
    __syncthreads();
    float tot = 0.0f;
    #pragma unroll
    for (int i = 0; i < 8; i++) tot += red[i];

    const float inv = 1.0f / sqrtf(tot);
    *(float4*)(out + base + t * 4) =
        make_float4(y0 * inv, y1 * inv, y2 * inv, y3 * inv);
}

// ---------------------------------------------------------------------------
// Launch
// ---------------------------------------------------------------------------
extern "C" void kernel_launch(void* const* d_in, const int* in_sizes, int n_in,
                              void* d_out, int out_size)
{
    const float* x  = (const float*)d_in[0];
    const float* Wq = (const float*)d_in[1];
    const float* Wk = (const float*)d_in[2];
    const float* Wv = (const float*)d_in[3];
    float* out = (float*)d_out;

    bf16 *xhi, *xlo, *Wqthi, *Wqtlo, *Wkthi, *Wktlo, *Mthi, *Mtlo;
    __half *x16, *zh16, *zl16, *Wvh, *Vt16, *Ph;
    float* Sc;
    cudaGetSymbolAddress((void**)&xhi,   g_xhi);    cudaGetSymbolAddress((void**)&xlo,   g_xlo);
    cudaGetSymbolAddress((void**)&Wqthi, g_Wqthi);  cudaGetSymbolAddress((void**)&Wqtlo, g_Wqtlo);
    cudaGetSymbolAddress((void**)&Wkthi, g_Wkthi);  cudaGetSymbolAddress((void**)&Wktlo, g_Wktlo);
    cudaGetSymbolAddress((void**)&Mthi,  g_Mthi);   cudaGetSymbolAddress((void**)&Mtlo,  g_Mtlo);
    cudaGetSymbolAddress((void**)&x16,   g_x16);
    cudaGetSymbolAddress((void**)&zh16,  g_zh16);   cudaGetSymbolAddress((void**)&zl16,  g_zl16);
    cudaGetSymbolAddress((void**)&Wvh,   g_Wvh);
    cudaGetSymbolAddress((void**)&Vt16,  g_Vt16);
    cudaGetSymbolAddress((void**)&Ph,    g_Ph);
    cudaGetSymbolAddress((void**)&Sc,    g_S);

    cudaFuncSetAttribute(gemm_bf, cudaFuncAttributeMaxDynamicSharedMemorySize, SMEM_DYN);
    cudaFuncSetAttribute(gemm_h2, cudaFuncAttributeMaxDynamicSharedMemorySize, H2_SMEM);
    cudaFuncSetAttribute(gemm_h1_n64, cudaFuncAttributeMaxDynamicSharedMemorySize, H1_SMEM);

    const size_t sQKV = (size_t)SLEN * DDIM;
    const size_t sSS  = (size_t)SLEN * SLEN;
    dim3 blk(256);

    // 0) conversions (x fused: one read -> bf16 hi/lo + fp16)
    conv_x<<<(MTOT * DDIM) / 1024, blk>>>(x, xhi, xlo, x16);
    conv_round16<<<(DDIM * DDIM) / 1024, blk>>>(Wv, Wvh);
    dim3 gtr(DDIM / 32, DDIM / 32, 1);
    trans_split<<<gtr, blk>>>(Wq, Wqthi, Wqtlo);
    trans_split<<<gtr, blk>>>(Wk, Wkthi, Wktlo);

    // 1) Mt = Wkt · Wqtᵀ  (bf16 3-pass, bf16 hi/lo out)
    dim3 gM(DDIM / 128, DDIM / 128, 1);
    gemm_bf<<<gM, blk, SMEM_DYN>>>(Wkthi, Wktlo, Wqthi, Wqtlo, Mthi, Mtlo,
                                   DDIM, DDIM, DDIM, DDIM, 1);

    // 2) z = x · Mtᵀ  (bf16 3-pass, fp16 hi/lo out for the scores GEMM)
    dim3 gz(DDIM / 128, MTOT / 128, 1);
    gemm_bf<<<gz, blk, SMEM_DYN>>>(xhi, xlo, Mthi, Mtlo,
                                   (bf16*)zh16, (bf16*)zl16,
                                   DDIM, DDIM, DDIM, DDIM, 4);

    // 3) Vt = Wvh · x16ᵀ  (fp16 1-pass, 128x64 tiles, fp16 out)
    dim3 gv(MTOT / 64, DDIM / 128, 1);       // (256, 8) = 2048 CTAs
    gemm_h1_n64<<<gv, blk, H1_SMEM>>>(Wvh, x16, nullptr, Vt16,
                                      DDIM, DDIM, MTOT, DDIM, 3, 0, 0, 0);

    // 4) scores = z · x16ᵀ per batch (fp16 2-pass, fp32 out)
    dim3 gsc(SLEN / 128, SLEN / 128, BATCH);
    gemm_h2<<<gsc, blk, H2_SMEM>>>(zh16, zl16, x16, Sc,
                                   DDIM, DDIM, SLEN, DDIM, sQKV, sQKV, sSS);

    // 5) softmax -> P fp16 rounded (BETA = 1)
    softmax_kernel16<<<MTOT, blk>>>(Sc, Ph);

    // 6) attended = P16 · Vt16ᵀ per batch (fp16 1-pass, 128x64 tiles)
    dim3 gav(DDIM / 64, SLEN / 128, BATCH);  // (16, 32, 4) = 2048 CTAs
    gemm_h1_n64<<<gav, blk, H1_SMEM>>>(Ph, Vt16, out, nullptr,
                                       SLEN, MTOT, DDIM, SLEN, 0,
                                       sSS, (size_t)SLEN, sQKV);

    // 7) y = attended + x; L2 normalize
    epilogue_kernel<<<MTOT, blk>>>(x, out);
}

// round 17
// speedup vs baseline: 1.1410x; 1.1410x over previous
#include <cuda_runtime.h>
#include <cuda_bf16.h>
#include <cuda_fp16.h>
#include <cstdint>
#include <cstddef>

#define BATCH   4
#define SLEN    4096
#define DDIM    1024
#define MTOT    (BATCH * SLEN)          // 16384

typedef __nv_bfloat16  bf16;
typedef __nv_bfloat162 bf162;

// ---------------------------------------------------------------------------
// Scratch (allocation-free rule: __device__ globals).
// z path (bf16 3-pass):   z = x·M, M = Wqᵀ·Wk           (K projection gone)
// scores (fp16 2-pass):   scores = (zh+zl)·x16ᵀ  (fp32 out)
// PV path (fp16 1-pass):  Vᵀ = Wvh·x16ᵀ, attended = P16·Vᵀᵀ
// z and Vᵀ run fused in one launch (wave packing).
// ---------------------------------------------------------------------------
__device__ bf16 g_xhi [(size_t)MTOT * DDIM];
__device__ bf16 g_xlo [(size_t)MTOT * DDIM];
__device__ bf16 g_Wqthi[(size_t)DDIM * DDIM];
__device__ bf16 g_Wqtlo[(size_t)DDIM * DDIM];
__device__ bf16 g_Wkthi[(size_t)DDIM * DDIM];
__device__ bf16 g_Wktlo[(size_t)DDIM * DDIM];
__device__ bf16 g_Mthi[(size_t)DDIM * DDIM];
__device__ bf16 g_Mtlo[(size_t)DDIM * DDIM];
__device__ float g_S  [(size_t)MTOT * SLEN];
// fp16 operands
__device__ __half g_x16 [(size_t)MTOT * DDIM];   // x rounded to fp16
__device__ __half g_zh16[(size_t)MTOT * DDIM];   // z split fp16
__device__ __half g_zl16[(size_t)MTOT * DDIM];
__device__ __half g_Wvh [(size_t)DDIM * DDIM];   // Wv rounded fp16
__device__ __half g_Vt16[(size_t)DDIM * MTOT];   // Vᵀ fp16 [D, MTOT]
__device__ __half g_Ph  [(size_t)MTOT * SLEN];   // P rounded fp16

// ---------------------------------------------------------------------------
// Helpers (arch-agnostic PTX only: plain sm_103 target)
// ---------------------------------------------------------------------------
__device__ __forceinline__ uint32_t smem_u32(const void* p) {
    uint32_t a;
    asm("{ .reg .u64 t; cvta.to.shared.u64 t, %1; cvt.u32.u64 %0, t; }" : "=r"(a) : "l"(p));
    return a;
}
__device__ __forceinline__ void ldsm4(uint32_t& r0, uint32_t& r1, uint32_t& r2, uint32_t& r3,
                                      uint32_t addr) {
    asm volatile("ldmatrix.sync.aligned.m8n8.x4.shared.b16 {%0,%1,%2,%3}, [%4];"
                 : "=r"(r0), "=r"(r1), "=r"(r2), "=r"(r3) : "r"(addr));
}
__device__ __forceinline__ void mma16816(float* c, const uint32_t* a, const uint32_t* b) {
    asm volatile(
        "mma.sync.aligned.m16n8k16.row.col.f32.bf16.bf16.f32 "
        "{%0,%1,%2,%3}, {%4,%5,%6,%7}, {%8,%9}, {%0,%1,%2,%3};"
        : "+f"(c[0]), "+f"(c[1]), "+f"(c[2]), "+f"(c[3])
        : "r"(a[0]), "r"(a[1]), "r"(a[2]), "r"(a[3]), "r"(b[0]), "r"(b[1]));
}
__device__ __forceinline__ void mma16816h(float* c, const uint32_t* a, const uint32_t* b) {
    asm volatile(
        "mma.sync.aligned.m16n8k16.row.col.f32.f16.f16.f32 "
        "{%0,%1,%2,%3}, {%4,%5,%6,%7}, {%8,%9}, {%0,%1,%2,%3};"
        : "+f"(c[0]), "+f"(c[1]), "+f"(c[2]), "+f"(c[3])
        : "r"(a[0]), "r"(a[1]), "r"(a[2]), "r"(a[3]), "r"(b[0]), "r"(b[1]));
}
__device__ __forceinline__ void cpasync16(uint32_t dst, const void* src) {
    asm volatile("cp.async.cg.shared.global [%0], [%1], 16;" :: "r"(dst), "l"(src));
}
__device__ __forceinline__ void split2(float x, float y, bf162& h, bf162& l) {
    h = __floats2bfloat162_rn(x, y);
    float2 f = __bfloat1622float2(h);
    l = __floats2bfloat162_rn(x - f.x, y - f.y);
}
__device__ __forceinline__ void split2h(float x, float y, __half2& h, __half2& l) {
    h = __floats2half2_rn(x, y);
    float2 f = __half22float2(h);
    l = __floats2half2_rn(x - f.x, y - f.y);
}

// ---------------------------------------------------------------------------
// Fused conversion for x: one read -> bf16 hi/lo + fp16 rounded.
// ---------------------------------------------------------------------------
__global__ __launch_bounds__(256) void conv_x(
    const float* __restrict__ src, bf16* __restrict__ hi, bf16* __restrict__ lo,
    __half* __restrict__ h16)
{
    size_t i = ((size_t)blockIdx.x * 256 + threadIdx.x) * 4;
    float4 v = *(const float4*)(src + i);
    bf162 h0, l0, h1, l1;
    split2(v.x, v.y, h0, l0);
    split2(v.z, v.w, h1, l1);
    *(bf162*)(hi + i)     = h0;
    *(bf162*)(hi + i + 2) = h1;
    *(bf162*)(lo + i)     = l0;
    *(bf162*)(lo + i + 2) = l1;
    *(__half2*)(h16 + i)     = __floats2half2_rn(v.x, v.y);
    *(__half2*)(h16 + i + 2) = __floats2half2_rn(v.z, v.w);
}

__global__ __launch_bounds__(256) void conv_round16(
    const float* __restrict__ src, __half* __restrict__ dst)
{
    size_t i = ((size_t)blockIdx.x * 256 + threadIdx.x) * 4;
    float4 v = *(const float4*)(src + i);
    *(__half2*)(dst + i)     = __floats2half2_rn(v.x, v.y);
    *(__half2*)(dst + i + 2) = __floats2half2_rn(v.z, v.w);
}

// Transpose + split: out[i,e] = src[e,i] for 1024x1024 fp32, bf16 hi/lo out.
__global__ __launch_bounds__(256) void trans_split(
    const float* __restrict__ src, bf16* __restrict__ hi, bf16* __restrict__ lo)
{
    __shared__ float t[32][33];
    const int tx = threadIdx.x & 31;
    const int ty = threadIdx.x >> 5;
    const int bx = blockIdx.x * 32;
    const int by = blockIdx.y * 32;
    #pragma unroll
    for (int i = 0; i < 4; i++)
        t[ty + i * 8][tx] = src[(size_t)(by + ty + i * 8) * DDIM + bx + tx];
    __syncthreads();
    #pragma unroll
    for (int i = 0; i < 4; i++) {
        const int r = ty + i * 8;
        float v = t[tx][r];
        bf16 h = __float2bfloat16_rn(v);
        bf16 l = __float2bfloat16_rn(v - __bfloat162float(h));
        hi[(size_t)(bx + r) * DDIM + by + tx] = h;
        lo[(size_t)(bx + r) * DDIM + by + tx] = l;
    }
}

// ---------------------------------------------------------------------------
// Common tile constants
// ---------------------------------------------------------------------------
#define KC       32
#define LDT      40
#define MAT_B    (128 * LDT * 2)            // 10240 B
#define STAGE_B  (4 * MAT_B)                // 40960 B
#define SMEM_DYN (2 * STAGE_B)              // 81920 B
#define H2_STAGE (3 * MAT_B)                // 30720 B
#define H2_SMEM  (2 * H2_STAGE)             // 61440 B
#define H1_STAGE (2 * MAT_B)                // 20480 B
#define H1_SMEM  (2 * H1_STAGE)             // 40960 B

// ---------------------------------------------------------------------------
// bf16 NT GEMM, 3-pass fp32 emulation. 128x128, KC=32, 2-stage cp.async,
// 2 CTAs/SM. mode 1: bf16 hi/lo out. (used for Mt only)
// ---------------------------------------------------------------------------
__global__ __launch_bounds__(256, 2) void gemm_bf(
    const bf16* __restrict__ Ahi, const bf16* __restrict__ Alo,
    const bf16* __restrict__ Bhi, const bf16* __restrict__ Blo,
    bf16* __restrict__ Chi, bf16* __restrict__ Clo,
    int lda, int ldb, int ldc, int K)
{
    extern __shared__ char smem[];

    const int tid  = threadIdx.x;
    const int lane = tid & 31;
    const int wid  = tid >> 5;
    const int bm   = blockIdx.y * 128;
    const int bn   = blockIdx.x * 128;
    const int m_warp = (wid & 3) * 32;
    const int n_warp = (wid >> 2) * 64;

    const uint32_t sbase = smem_u32(smem);
    const uint32_t aoff = (uint32_t)((m_warp + (lane & 15)) * (LDT * 2) + ((lane >> 4) * 8) * 2);
    const uint32_t boff = (uint32_t)((n_warp + (lane & 7) + ((lane & 16) ? 8 : 0)) * (LDT * 2)
                                     + ((lane & 8) ? 8 : 0) * 2);

    float acc[2][8][4];
    #pragma unroll
    for (int t = 0; t < 2; t++)
        #pragma unroll
        for (int n = 0; n < 8; n++)
            #pragma unroll
            for (int q = 0; q < 4; q++) acc[t][n][q] = 0.0f;

    const int nk = K / KC;

    auto issue = [&](int buf, int c) {
        const int k0 = c * KC;
        const uint32_t sb = sbase + buf * STAGE_B;
        #pragma unroll
        for (int i = 0; i < 2; i++) {
            const int l   = tid + i * 256;
            const int row = l >> 2;
            const int ch  = (l & 3) * 16;
            const uint32_t soff = (uint32_t)(row * (LDT * 2)) + ch;
            const size_t ga = (size_t)(bm + row) * lda + k0;
            const size_t gb = (size_t)(bn + row) * ldb + k0;
            cpasync16(sb + 0 * MAT_B + soff, (const char*)(Ahi + ga) + ch);
            cpasync16(sb + 1 * MAT_B + soff, (const char*)(Alo + ga) + ch);
            cpasync16(sb + 2 * MAT_B + soff, (const char*)(Bhi + gb) + ch);
            cpasync16(sb + 3 * MAT_B + soff, (const char*)(Blo + gb) + ch);
        }
    };

    auto compute = [&](int buf) {
        const uint32_t base = sbase + buf * STAGE_B;
        #pragma unroll
        for (int ks = 0; ks < 2; ks++) {
            const uint32_t kb = (uint32_t)ks * 32;
            uint32_t bh[4][4], bl[4][4];
            #pragma unroll
            for (int u = 0; u < 4; u++) {
                ldsm4(bh[u][0], bh[u][1], bh[u][2], bh[u][3],
                      base + 2 * MAT_B + boff + u * (16 * LDT * 2) + kb);
                ldsm4(bl[u][0], bl[u][1], bl[u][2], bl[u][3],
                      base + 3 * MAT_B + boff + u * (16 * LDT * 2) + kb);
            }
            #pragma unroll
            for (int t = 0; t < 2; t++) {
                uint32_t ah[4], al[4];
                ldsm4(ah[0], ah[1], ah[2], ah[3],
                      base + 0 * MAT_B + aoff + t * (16 * LDT * 2) + kb);
                ldsm4(al[0], al[1], al[2], al[3],
                      base + 1 * MAT_B + aoff + t * (16 * LDT * 2) + kb);
                #pragma unroll
                for (int n = 0; n < 8; n++)
                    mma16816(acc[t][n], ah, &bh[n >> 1][(n & 1) * 2]);
                #pragma unroll
                for (int n = 0; n < 8; n++)
                    mma16816(acc[t][n], ah, &bl[n >> 1][(n & 1) * 2]);
                #pragma unroll
                for (int n = 0; n < 8; n++)
                    mma16816(acc[t][n], al, &bh[n >> 1][(n & 1) * 2]);
            }
        }
    };

    issue(0, 0);
    asm volatile("cp.async.commit_group;" ::: "memory");

    for (int c = 0; c < nk; ++c) {
        asm volatile("cp.async.wait_group 0;" ::: "memory");
        __syncthreads();
        if (c + 1 < nk) {
            issue((c + 1) & 1, c + 1);
            asm volatile("cp.async.commit_group;" ::: "memory");
        }
        compute(c & 1);
    }

    #pragma unroll
    for (int t = 0; t < 2; t++)
        #pragma unroll
        for (int n = 0; n < 8; n++) {
            const int row = bm + m_warp + t * 16 + (lane >> 2);
            const int col = bn + n_warp + n * 8 + (lane & 3) * 2;
            bf162 h, l;
            split2(acc[t][n][0], acc[t][n][1], h, l);
            *(bf162*)(Chi + (size_t)row * ldc + col) = h;
            *(bf162*)(Clo + (size_t)row * ldc + col) = l;
            split2(acc[t][n][2], acc[t][n][3], h, l);
            *(bf162*)(Chi + (size_t)(row + 8) * ldc + col) = h;
            *(bf162*)(Clo + (size_t)(row + 8) * ldc + col) = l;
        }
}

// ---------------------------------------------------------------------------
// FUSED kernel: z (bf16 3-pass, fp16 hi/lo out) and Vt (fp16 1-pass, fp16 out)
// in one launch for wave packing. bid < 1024: z tile; else Vt tile.
// ---------------------------------------------------------------------------
__global__ __launch_bounds__(256, 2) void gemm_zv(
    const bf16* __restrict__ xhi, const bf16* __restrict__ xlo,
    const bf16* __restrict__ Mthi, const bf16* __restrict__ Mtlo,
    __half* __restrict__ zh, __half* __restrict__ zl,
    const __half* __restrict__ Wvh, const __half* __restrict__ x16,
    __half* __restrict__ Vt)
{
    extern __shared__ char smem[];
    const int tid  = threadIdx.x;
    const int lane = tid & 31;
    const int wid  = tid >> 5;
    const int m_warp = (wid & 3) * 32;
    const int n_warp = (wid >> 2) * 64;

    const uint32_t sbase = smem_u32(smem);
    const uint32_t aoff = (uint32_t)((m_warp + (lane & 15)) * (LDT * 2) + ((lane >> 4) * 8) * 2);
    const uint32_t boff = (uint32_t)((n_warp + (lane & 7) + ((lane & 16) ? 8 : 0)) * (LDT * 2)
                                     + ((lane & 8) ? 8 : 0) * 2);
    const int nk = DDIM / KC;
    const int bid = blockIdx.x;

    if (bid < 1024) {
        // ---- z path: z = x · Mtᵀ, 128x128 tile, bf16 3-pass ----
        const int bm = (bid >> 3) * 128;      // 128 M-tiles
        const int bn = (bid & 7) * 128;       // 8 N-tiles

        float acc[2][8][4];
        #pragma unroll
        for (int t = 0; t < 2; t++)
            #pragma unroll
            for (int n = 0; n < 8; n++)
                #pragma unroll
                for (int q = 0; q < 4; q++) acc[t][n][q] = 0.0f;

        auto issue = [&](int buf, int c) {
            const int k0 = c * KC;
            const uint32_t sb = sbase + buf * STAGE_B;
            #pragma unroll
            for (int i = 0; i < 2; i++) {
                const int l   = tid + i * 256;
                const int row = l >> 2;
                const int ch  = (l & 3) * 16;
                const uint32_t soff = (uint32_t)(row * (LDT * 2)) + ch;
                const size_t ga = (size_t)(bm + row) * DDIM + k0;
                const size_t gb = (size_t)(bn + row) * DDIM + k0;
                cpasync16(sb + 0 * MAT_B + soff, (const char*)(xhi + ga) + ch);
                cpasync16(sb + 1 * MAT_B + soff, (const char*)(xlo + ga) + ch);
                cpasync16(sb + 2 * MAT_B + soff, (const char*)(Mthi + gb) + ch);
                cpasync16(sb + 3 * MAT_B + soff, (const char*)(Mtlo + gb) + ch);
            }
        };

        auto compute = [&](int buf) {
            const uint32_t base = sbase + buf * STAGE_B;
            #pragma unroll
            for (int ks = 0; ks < 2; ks++) {
                const uint32_t kb = (uint32_t)ks * 32;
                uint32_t bh[4][4], bl[4][4];
                #pragma unroll
                for (int u = 0; u < 4; u++) {
                    ldsm4(bh[u][0], bh[u][1], bh[u][2], bh[u][3],
                          base + 2 * MAT_B + boff + u * (16 * LDT * 2) + kb);
                    ldsm4(bl[u][0], bl[u][1], bl[u][2], bl[u][3],
                          base + 3 * MAT_B + boff + u * (16 * LDT * 2) + kb);
                }
                #pragma unroll
                for (int t = 0; t < 2; t++) {
                    uint32_t ah[4], al[4];
                    ldsm4(ah[0], ah[1], ah[2], ah[3],
                          base + 0 * MAT_B + aoff + t * (16 * LDT * 2) + kb);
                    ldsm4(al[0], al[1], al[2], al[3],
                          base + 1 * MAT_B + aoff + t * (16 * LDT * 2) + kb);
                    #pragma unroll
                    for (int n = 0; n < 8; n++)
                        mma16816(acc[t][n], ah, &bh[n >> 1][(n & 1) * 2]);
                    #pragma unroll
                    for (int n = 0; n < 8; n++)
                        mma16816(acc[t][n], ah, &bl[n >> 1][(n & 1) * 2]);
                    #pragma unroll
                    for (int n = 0; n < 8; n++)
                        mma16816(acc[t][n], al, &bh[n >> 1][(n & 1) * 2]);
                }
            }
        };

        issue(0, 0);
        asm volatile("cp.async.commit_group;" ::: "memory");
        for (int c = 0; c < nk; ++c) {
            asm volatile("cp.async.wait_group 0;" ::: "memory");
            __syncthreads();
            if (c + 1 < nk) {
                issue((c + 1) & 1, c + 1);
                asm volatile("cp.async.commit_group;" ::: "memory");
            }
            compute(c & 1);
        }

        #pragma unroll
        for (int t = 0; t < 2; t++)
            #pragma unroll
            for (int n = 0; n < 8; n++) {
                const int row = bm + m_warp + t * 16 + (lane >> 2);
                const int col = bn + n_warp + n * 8 + (lane & 3) * 2;
                __half2 h, l;
                split2h(acc[t][n][0], acc[t][n][1], h, l);
                *(__half2*)(zh + (size_t)row * DDIM + col) = h;
                *(__half2*)(zl + (size_t)row * DDIM + col) = l;
                split2h(acc[t][n][2], acc[t][n][3], h, l);
                *(__half2*)(zh + (size_t)(row + 8) * DDIM + col) = h;
                *(__half2*)(zl + (size_t)(row + 8) * DDIM + col) = l;
            }
    } else {
        // ---- Vt path: Vt = Wvh · x16ᵀ, 128x128 tile, fp16 1-pass ----
        const int v  = bid - 1024;
        const int bm = (v >> 7) * 128;        // 8 D-tiles
        const int bn = (v & 127) * 128;       // 128 MTOT-tiles

        float acc[2][8][4];
        #pragma unroll
        for (int t = 0; t < 2; t++)
            #pragma unroll
            for (int n = 0; n < 8; n++)
                #pragma unroll
                for (int q = 0; q < 4; q++) acc[t][n][q] = 0.0f;

        auto issue = [&](int buf, int c) {
            const int k0 = c * KC;
            const uint32_t sb = sbase + buf * H1_STAGE;
            #pragma unroll
            for (int i = 0; i < 2; i++) {
                const int l   = tid + i * 256;
                const int row = l >> 2;
                const int ch  = (l & 3) * 16;
                const uint32_t soff = (uint32_t)(row * (LDT * 2)) + ch;
                const size_t ga = (size_t)(bm + row) * DDIM + k0;
                const size_t gb = (size_t)(bn + row) * DDIM + k0;
                cpasync16(sb + 0 * MAT_B + soff, (const char*)(Wvh + ga) + ch);
                cpasync16(sb + 1 * MAT_B + soff, (const char*)(x16 + gb) + ch);
            }
        };

        auto compute = [&](int buf) {
            const uint32_t base = sbase + buf * H1_STAGE;
            #pragma unroll
            for (int ks = 0; ks < 2; ks++) {
                const uint32_t kb = (uint32_t)ks * 32;
                uint32_t bh[4][4];
                #pragma unroll
                for (int u = 0; u < 4; u++)
                    ldsm4(bh[u][0], bh[u][1], bh[u][2], bh[u][3],
                          base + 1 * MAT_B + boff + u * (16 * LDT * 2) + kb);
                #pragma unroll
                for (int t = 0; t < 2; t++) {
                    uint32_t ah[4];
                    ldsm4(ah[0], ah[1], ah[2], ah[3],
                          base + 0 * MAT_B + aoff + t * (16 * LDT * 2) + kb);
                    #pragma unroll
                    for (int n = 0; n < 8; n++)
                        mma16816h(acc[t][n], ah, &bh[n >> 1][(n & 1) * 2]);
                }
            }
        };

        issue(0, 0);
        asm volatile("cp.async.commit_group;" ::: "memory");
        for (int c = 0; c < nk; ++c) {
            asm volatile("cp.async.wait_group 0;" ::: "memory");
            __syncthreads();
            if (c + 1 < nk) {
                issue((c + 1) & 1, c + 1);
                asm volatile("cp.async.commit_group;" ::: "memory");
            }
            compute(c & 1);
        }

        #pragma unroll
        for (int t = 0; t < 2; t++)
            #pragma unroll
            for (int n = 0; n < 8; n++) {
                const int row = bm + m_warp + t * 16 + (lane >> 2);
                const int col = bn + n_warp + n * 8 + (lane & 3) * 2;
                *(__half2*)(Vt + (size_t)row * MTOT + col) =
                    __floats2half2_rn(acc[t][n][0], acc[t][n][1]);
                *(__half2*)(Vt + (size_t)(row + 8) * MTOT + col) =
                    __floats2half2_rn(acc[t][n][2], acc[t][n][3]);
            }
    }
}

// ---------------------------------------------------------------------------
// fp16 NT GEMM, 2-pass (A split fp16, B rounded fp16), fp32 out (scores).
// ---------------------------------------------------------------------------
__global__ __launch_bounds__(256, 2) void gemm_h2(
    const __half* __restrict__ Ah, const __half* __restrict__ Al,
    const __half* __restrict__ Bh,
    float* __restrict__ Cf,
    int lda, int ldb, int ldc, int K,
    size_t sA, size_t sB, size_t sC)
{
    extern __shared__ char smem[];
    Ah += (size_t)blockIdx.z * sA;  Al += (size_t)blockIdx.z * sA;
    Bh += (size_t)blockIdx.z * sB;

    const int tid  = threadIdx.x;
    const int lane = tid & 31;
    const int wid  = tid >> 5;
    const int bm   = blockIdx.y * 128;
    const int bn   = blockIdx.x * 128;
    const int m_warp = (wid & 3) * 32;
    const int n_warp = (wid >> 2) * 64;

    const uint32_t sbase = smem_u32(smem);
    const uint32_t aoff = (uint32_t)((m_warp + (lane & 15)) * (LDT * 2) + ((lane >> 4) * 8) * 2);
    const uint32_t boff = (uint32_t)((n_warp + (lane & 7) + ((lane & 16) ? 8 : 0)) * (LDT * 2)
                                     + ((lane & 8) ? 8 : 0) * 2);

    float acc[2][8][4];
    #pragma unroll
    for (int t = 0; t < 2; t++)
        #pragma unroll
        for (int n = 0; n < 8; n++)
            #pragma unroll
            for (int q = 0; q < 4; q++) acc[t][n][q] = 0.0f;

    const int nk = K / KC;

    auto issue = [&](int buf, int c) {
        const int k0 = c * KC;
        const uint32_t sb = sbase + buf * H2_STAGE;
        #pragma unroll
        for (int i = 0; i < 2; i++) {
            const int l   = tid + i * 256;
            const int row = l >> 2;
            const int ch  = (l & 3) * 16;
            const uint32_t soff = (uint32_t)(row * (LDT * 2)) + ch;
            const size_t ga = (size_t)(bm + row) * lda + k0;
            const size_t gb = (size_t)(bn + row) * ldb + k0;
            cpasync16(sb + 0 * MAT_B + soff, (const char*)(Ah + ga) + ch);
            cpasync16(sb + 1 * MAT_B + soff, (const char*)(Al + ga) + ch);
            cpasync16(sb + 2 * MAT_B + soff, (const char*)(Bh + gb) + ch);
        }
    };

    auto compute = [&](int buf) {
        const uint32_t base = sbase + buf * H2_STAGE;
        #pragma unroll
        for (int ks = 0; ks < 2; ks++) {
            const uint32_t kb = (uint32_t)ks * 32;
            uint32_t bh[4][4];
            #pragma unroll
            for (int u = 0; u < 4; u++)
                ldsm4(bh[u][0], bh[u][1], bh[u][2], bh[u][3],
                      base + 2 * MAT_B + boff + u * (16 * LDT * 2) + kb);
            #pragma unroll
            for (int t = 0; t < 2; t++) {
                uint32_t ah[4], al[4];
                ldsm4(ah[0], ah[1], ah[2], ah[3],
                      base + 0 * MAT_B + aoff + t * (16 * LDT * 2) + kb);
                ldsm4(al[0], al[1], al[2], al[3],
                      base + 1 * MAT_B + aoff + t * (16 * LDT * 2) + kb);
                #pragma unroll
                for (int n = 0; n < 8; n++)
                    mma16816h(acc[t][n], ah, &bh[n >> 1][(n & 1) * 2]);
                #pragma unroll
                for (int n = 0; n < 8; n++)
                    mma16816h(acc[t][n], al, &bh[n >> 1][(n & 1) * 2]);
            }
        }
    };

    issue(0, 0);
    asm volatile("cp.async.commit_group;" ::: "memory");

    for (int c = 0; c < nk; ++c) {
        asm volatile("cp.async.wait_group 0;" ::: "memory");
        __syncthreads();
        if (c + 1 < nk) {
            issue((c + 1) & 1, c + 1);
            asm volatile("cp.async.commit_group;" ::: "memory");
        }
        compute(c & 1);
    }

    float* C0 = Cf + (size_t)blockIdx.z * sC;
    #pragma unroll
    for (int t = 0; t < 2; t++)
        #pragma unroll
        for (int n = 0; n < 8; n++) {
            const int row = bm + m_warp + t * 16 + (lane >> 2);
            const int col = bn + n_warp + n * 8 + (lane & 3) * 2;
            *(float2*)(C0 + (size_t)row * ldc + col) =
                make_float2(acc[t][n][0], acc[t][n][1]);
            *(float2*)(C0 + (size_t)(row + 8) * ldc + col) =
                make_float2(acc[t][n][2], acc[t][n][3]);
        }
}

// ---------------------------------------------------------------------------
// fp16 NT GEMM, 1-pass (A rounded, B rounded), fp32 out. Used for PV.
// ---------------------------------------------------------------------------
__global__ __launch_bounds__(256, 2) void gemm_h1(
    const __half* __restrict__ Ah, const __half* __restrict__ Bh,
    float* __restrict__ Cf,
    int lda, int ldb, int ldc, int K,
    size_t sA, size_t sB, size_t sC)
{
    extern __shared__ char smem[];
    Ah += (size_t)blockIdx.z * sA;
    Bh += (size_t)blockIdx.z * sB;

    const int tid  = threadIdx.x;
    const int lane = tid & 31;
    const int wid  = tid >> 5;
    const int bm   = blockIdx.y * 128;
    const int bn   = blockIdx.x * 128;
    const int m_warp = (wid & 3) * 32;
    const int n_warp = (wid >> 2) * 64;

    const uint32_t sbase = smem_u32(smem);
    const uint32_t aoff = (uint32_t)((m_warp + (lane & 15)) * (LDT * 2) + ((lane >> 4) * 8) * 2);
    const uint32_t boff = (uint32_t)((n_warp + (lane & 7) + ((lane & 16) ? 8 : 0)) * (LDT * 2)
                                     + ((lane & 8) ? 8 : 0) * 2);

    float acc[2][8][4];
    #pragma unroll
    for (int t = 0; t < 2; t++)
        #pragma unroll
        for (int n = 0; n < 8; n++)
            #pragma unroll
            for (int q = 0; q < 4; q++) acc[t][n][q] = 0.0f;

    const int nk = K / KC;

    auto issue = [&](int buf, int c) {
        const int k0 = c * KC;
        const uint32_t sb = sbase + buf * H1_STAGE;
        #pragma unroll
        for (int i = 0; i < 2; i++) {
            const int l   = tid + i * 256;
            const int row = l >> 2;
            const int ch  = (l & 3) * 16;
            const uint32_t soff = (uint32_t)(row * (LDT * 2)) + ch;
            const size_t ga = (size_t)(bm + row) * lda + k0;
            const size_t gb = (size_t)(bn + row) * ldb + k0;
            cpasync16(sb + 0 * MAT_B + soff, (const char*)(Ah + ga) + ch);
            cpasync16(sb + 1 * MAT_B + soff, (const char*)(Bh + gb) + ch);
        }
    };

    auto compute = [&](int buf) {
        const uint32_t base = sbase + buf * H1_STAGE;
        #pragma unroll
        for (int ks = 0; ks < 2; ks++) {
            const uint32_t kb = (uint32_t)ks * 32;
            uint32_t bh[4][4];
            #pragma unroll
            for (int u = 0; u < 4; u++)
                ldsm4(bh[u][0], bh[u][1], bh[u][2], bh[u][3],
                      base + 1 * MAT_B + boff + u * (16 * LDT * 2) + kb);
            #pragma unroll
            for (int t = 0; t < 2; t++) {
                uint32_t ah[4];
                ldsm4(ah[0], ah[1], ah[2], ah[3],
                      base + aoff + t * (16 * LDT * 2) + kb);
                #pragma unroll
                for (int n = 0; n < 8; n++)
                    mma16816h(acc[t][n], ah, &bh[n >> 1][(n & 1) * 2]);
            }
        }
    };

    issue(0, 0);
    asm volatile("cp.async.commit_group;" ::: "memory");

    for (int c = 0; c < nk; ++c) {
        asm volatile("cp.async.wait_group 0;" ::: "memory");
        __syncthreads();
        if (c + 1 < nk) {
            issue((c + 1) & 1, c + 1);
            asm volatile("cp.async.commit_group;" ::: "memory");
        }
        compute(c & 1);
    }

    #pragma unroll
    for (int t = 0; t < 2; t++)
        #pragma unroll
        for (int n = 0; n < 8; n++) {
            const int row = bm + m_warp + t * 16 + (lane >> 2);
            const int col = bn + n_warp + n * 8 + (lane & 3) * 2;
            float* C0 = Cf + (size_t)blockIdx.z * sC;
            *(float2*)(C0 + (size_t)row * ldc + col) =
                make_float2(acc[t][n][0], acc[t][n][1]);
            *(float2*)(C0 + (size_t)(row + 8) * ldc + col) =
                make_float2(acc[t][n][2], acc[t][n][3]);
        }
}

// ---------------------------------------------------------------------------
// Row softmax over 4096 fp32 scores -> fp16 rounded probabilities.
// ---------------------------------------------------------------------------
__global__ __launch_bounds__(256) void softmax_kernel16(
    const float* __restrict__ Sm, __half* __restrict__ Ph)
{
    const float* row = Sm + (size_t)blockIdx.x * SLEN;
    __half* ph = Ph + (size_t)blockIdx.x * SLEN;
    const int t    = threadIdx.x;
    const int lane = t & 31;
    const int warp = t >> 5;

    __shared__ float red[8];

    float v[16];
    float mx = -1e30f;
    #pragma unroll
    for (int i = 0; i < 16; i++) {
        v[i] = row[t + (i << 8)];
        mx = fmaxf(mx, v[i]);
    }
    #pragma unroll
    for (int o = 16; o > 0; o >>= 1)
        mx = fmaxf(mx, __shfl_xor_sync(0xffffffffu, mx, o));
    if (lane == 0) red[warp] = mx;
    __syncthreads();
    float rmax = red[0];
    #pragma unroll
    for (int i = 1; i < 8; i++) rmax = fmaxf(rmax, red[i]);

    float sum = 0.0f;
    #pragma unroll
    for (int i = 0; i < 16; i++) {
        v[i] = __expf(v[i] - rmax);
        sum += v[i];
    }
    #pragma unroll
    for (int o = 16; o > 0; o >>= 1)
        sum += __shfl_xor_sync(0xffffffffu, sum, o);
    __syncthreads();
    if (lane == 0) red[warp] = sum;
    __syncthreads();
    float rsum = 0.0f;
    #pragma unroll
    for (int i = 0; i < 8; i++) rsum += red[i];

    const float inv = 1.0f / rsum;
    #pragma unroll
    for (int i = 0; i < 16; i++)
        ph[t + (i << 8)] = __float2half_rn(v[i] * inv);
}

// ---------------------------------------------------------------------------
// Final epilogue: y = attended + x;  out = y / ||y||_2 per 1024-row.
// ---------------------------------------------------------------------------
__global__ __launch_bounds__(256) void epilogue_kernel(
    const float* __restrict__ x, float* __restrict__ out)
{
    const size_t base = (size_t)blockIdx.x * DDIM;
    const int t    = threadIdx.x;
    const int lane = t & 31;
    const int warp = t >> 5;

    __shared__ float red[8];

    float4 a  = *(const float4*)(out + base + t * 4);
    float4 xv = *(const float4*)(x   + base + t * 4);
    float y0 = a.x + xv.x, y1 = a.y + xv.y, y2 = a.z + xv.z, y3 = a.w + xv.w;

    float ss = y0 * y0 + y1 * y1 + y2 * y2 + y3 * y3;
    #pragma unroll
    for (int o = 16; o > 0; o >>= 1)
        ss += __shfl_xor_sync(0xffffffffu, ss, o);
    if (lane == 0) red[warp] = ss;
    __syncthreads();
    float tot = 0.0f;
    #pragma unroll
    for (int i = 0; i < 8; i++) tot += red[i];

    const float inv = 1.0f / sqrtf(tot);
    *(float4*)(out + base + t * 4) =
        make_float4(y0 * inv, y1 * inv, y2 * inv, y3 * inv);
}

// ---------------------------------------------------------------------------
// Launch
// ---------------------------------------------------------------------------
extern "C" void kernel_launch(void* const* d_in, const int* in_sizes, int n_in,
                              void* d_out, int out_size)
{
    const float* x  = (const float*)d_in[0];
    const float* Wq = (const float*)d_in[1];
    const float* Wk = (const float*)d_in[2];
    const float* Wv = (const float*)d_in[3];
    float* out = (float*)d_out;

    bf16 *xhi, *xlo, *Wqthi, *Wqtlo, *Wkthi, *Wktlo, *Mthi, *Mtlo;
    __half *x16, *zh16, *zl16, *Wvh, *Vt16, *Ph;
    float* Sc;
    cudaGetSymbolAddress((void**)&xhi,   g_xhi);    cudaGetSymbolAddress((void**)&xlo,   g_xlo);
    cudaGetSymbolAddress((void**)&Wqthi, g_Wqthi);  cudaGetSymbolAddress((void**)&Wqtlo, g_Wqtlo);
    cudaGetSymbolAddress((void**)&Wkthi, g_Wkthi);  cudaGetSymbolAddress((void**)&Wktlo, g_Wktlo);
    cudaGetSymbolAddress((void**)&Mthi,  g_Mthi);   cudaGetSymbolAddress((void**)&Mtlo,  g_Mtlo);
    cudaGetSymbolAddress((void**)&x16,   g_x16);
    cudaGetSymbolAddress((void**)&zh16,  g_zh16);   cudaGetSymbolAddress((void**)&zl16,  g_zl16);
    cudaGetSymbolAddress((void**)&Wvh,   g_Wvh);
    cudaGetSymbolAddress((void**)&Vt16,  g_Vt16);
    cudaGetSymbolAddress((void**)&Ph,    g_Ph);
    cudaGetSymbolAddress((void**)&Sc,    g_S);

    cudaFuncSetAttribute(gemm_bf, cudaFuncAttributeMaxDynamicSharedMemorySize, SMEM_DYN);
    cudaFuncSetAttribute(gemm_zv, cudaFuncAttributeMaxDynamicSharedMemorySize, SMEM_DYN);
    cudaFuncSetAttribute(gemm_h2, cudaFuncAttributeMaxDynamicSharedMemorySize, H2_SMEM);
    cudaFuncSetAttribute(gemm_h1, cudaFuncAttributeMaxDynamicSharedMemorySize, H1_SMEM);

    const size_t sQKV = (size_t)SLEN * DDIM;
    const size_t sSS  = (size_t)SLEN * SLEN;
    dim3 blk(256);

    // 0) conversions (x fused: one read -> bf16 hi/lo + fp16)
    conv_x<<<(MTOT * DDIM) / 1024, blk>>>(x, xhi, xlo, x16);
    conv_round16<<<(DDIM * DDIM) / 1024, blk>>>(Wv, Wvh);
    dim3 gtr(DDIM / 32, DDIM / 32, 1);
    trans_split<<<gtr, blk>>>(Wq, Wqthi, Wqtlo);
    trans_split<<<gtr, blk>>>(Wk, Wkthi, Wktlo);

    // 1) Mt = Wkt · Wqtᵀ  (bf16 3-pass, bf16 hi/lo out)
    dim3 gM(DDIM / 128, DDIM / 128, 1);
    gemm_bf<<<gM, blk, SMEM_DYN>>>(Wkthi, Wktlo, Wqthi, Wqtlo, Mthi, Mtlo,
                                   DDIM, DDIM, DDIM, DDIM);

    // 2+3) FUSED: z = x·Mtᵀ (fp16 hi/lo out) ∥ Vt = Wvh·x16ᵀ (fp16 out)
    gemm_zv<<<2048, blk, SMEM_DYN>>>(xhi, xlo, Mthi, Mtlo, zh16, zl16,
                                     Wvh, x16, Vt16);

    // 4) scores = z · x16ᵀ per batch (fp16 2-pass, fp32 out)
    dim3 gsc(SLEN / 128, SLEN / 128, BATCH);
    gemm_h2<<<gsc, blk, H2_SMEM>>>(zh16, zl16, x16, Sc,
                                   DDIM, DDIM, SLEN, DDIM, sQKV, sQKV, sSS);

    // 5) softmax -> P fp16 rounded (BETA = 1)
    softmax_kernel16<<<MTOT, blk>>>(Sc, Ph);

    // 6) attended = P16 · Vt16ᵀ per batch (fp16 1-pass, fp32 out into d_out)
    dim3 gav(DDIM / 128, SLEN / 128, BATCH);
    gemm_h1<<<gav, blk, H1_SMEM>>>(Ph, Vt16, out,
                                   SLEN, MTOT, DDIM, SLEN,
                                   sSS, (size_t)SLEN, sQKV);

    // 7) y = attended + x; L2 normalize
    epilogue_kernel<<<MTOT, blk>>>(x, out);
}